// round 1
// baseline (speedup 1.0000x reference)
#include <cuda_runtime.h>
#include <cuda_bf16.h>
#include <cstdint>
#include <cmath>

// ---------------- problem constants ----------------
#define T_TOK   4096     // B*S
#define D_MODEL 1024
#define E_NUM   8
#define K_TOP   2
#define CAPACITY 1280    // floor(K*1.25*T/E), even
#define H_DIM   4096     // 4*D

// ---------------- device scratch (static globals; no runtime alloc) ------
__device__ float g_xe  [(size_t)E_NUM * CAPACITY * D_MODEL];  // dispatched tokens
__device__ float g_h   [(size_t)E_NUM * CAPACITY * H_DIM];    // gelu(fc) activations
__device__ float g_oute[(size_t)E_NUM * CAPACITY * D_MODEL];  // expert outputs
__device__ int   g_topi[K_TOP * T_TOK];   // k-major: [k*T + t]
__device__ float g_p   [K_TOP * T_TOK];   // top-2 softmax weights (k-major)
__device__ int   g_rank[K_TOP * T_TOK];   // capacity slot or -1 (dropped)
__device__ float g_prob_sums[E_NUM];      // sum over tokens of full-softmax probs
__device__ float g_zsum;                  // sum over tokens of lse^2

// ---------------- init ----------------
__global__ void init_kernel() {
    int i = threadIdx.x;
    if (i < E_NUM) g_prob_sums[i] = 0.f;
    if (i == 0)    g_zsum = 0.f;
}

// ---------------- router: logits, full softmax stats, top-2 ----------------
__global__ void router_kernel(const float* __restrict__ x,
                              const float* __restrict__ wg) {
    const int t = blockIdx.x;
    const float* xr = x + (size_t)t * D_MODEL;

    float acc[E_NUM];
#pragma unroll
    for (int e = 0; e < E_NUM; e++) acc[e] = 0.f;

    for (int d = threadIdx.x; d < D_MODEL; d += 128) {
        float xv = xr[d];
        const float* w = wg + d * E_NUM;
#pragma unroll
        for (int e = 0; e < E_NUM; e++) acc[e] += xv * w[e];
    }

    __shared__ float red[E_NUM][128];
#pragma unroll
    for (int e = 0; e < E_NUM; e++) red[e][threadIdx.x] = acc[e];
    __syncthreads();

    __shared__ float logit[E_NUM];
    if (threadIdx.x < E_NUM) {
        float s = 0.f;
        for (int i = 0; i < 128; i++) s += red[threadIdx.x][i];
        logit[threadIdx.x] = s;
    }
    __syncthreads();

    if (threadIdx.x == 0) {
        float l[E_NUM];
#pragma unroll
        for (int e = 0; e < E_NUM; e++) l[e] = logit[e];

        // full softmax stats (lb loss) + logsumexp^2 (z loss)
        float m = l[0];
#pragma unroll
        for (int e = 1; e < E_NUM; e++) m = fmaxf(m, l[e]);
        float se = 0.f;
#pragma unroll
        for (int e = 0; e < E_NUM; e++) se += expf(l[e] - m);
        float inv = 1.f / se;
#pragma unroll
        for (int e = 0; e < E_NUM; e++)
            atomicAdd(&g_prob_sums[e], expf(l[e] - m) * inv);
        float lse = m + logf(se);
        atomicAdd(&g_zsum, lse * lse);

        // top-2 (strict > => lower index wins ties, matching lax.top_k)
        float v1 = -3.4e38f, v2 = -3.4e38f;
        int i1 = 0, i2 = 0;
#pragma unroll
        for (int e = 0; e < E_NUM; e++) {
            float v = l[e];
            if (v > v1) { v2 = v1; i2 = i1; v1 = v; i1 = e; }
            else if (v > v2) { v2 = v; i2 = e; }
        }
        // softmax over masked logits == softmax over {v1, v2}
        float e2 = expf(v2 - v1);
        float s2 = 1.f + e2;
        g_topi[t]          = i1;
        g_topi[T_TOK + t]  = i2;
        g_p[t]             = 1.f / s2;
        g_p[T_TOK + t]     = e2 / s2;
    }
}

// ---------------- capacity assignment (exact k-major cumsum order) --------
__global__ void assign_kernel(float* __restrict__ out, int write_tail) {
    __shared__ int hist[256][E_NUM];
    __shared__ int tot[E_NUM];
    const int tid = threadIdx.x;
    const int base = tid * 32;             // 256 threads * 32 = K*T = 8192

    int cnt[E_NUM];
#pragma unroll
    for (int e = 0; e < E_NUM; e++) cnt[e] = 0;
    for (int j = 0; j < 32; j++) cnt[g_topi[base + j]]++;
#pragma unroll
    for (int e = 0; e < E_NUM; e++) hist[tid][e] = cnt[e];
    __syncthreads();

    if (tid < E_NUM) {
        int s = 0;
        for (int i = 0; i < 256; i++) { int c = hist[i][tid]; hist[i][tid] = s; s += c; }
        tot[tid] = s;
    }
    __syncthreads();

    int run[E_NUM];
#pragma unroll
    for (int e = 0; e < E_NUM; e++) run[e] = hist[tid][e];
    for (int j = 0; j < 32; j++) {
        int idx = base + j;
        int e = g_topi[idx];
        int r = run[e]++;
        g_rank[idx] = (r < CAPACITY) ? r : -1;
    }

    if (tid == 0 && write_tail) {
        float lb = 0.f;
#pragma unroll
        for (int e = 0; e < E_NUM; e++) {
            int kc = tot[e] < CAPACITY ? tot[e] : CAPACITY;
            lb += (g_prob_sums[e] / (float)T_TOK) *
                  ((float)kc / (float)(T_TOK * K_TOP));
        }
        lb *= (float)E_NUM;
        out[(size_t)T_TOK * D_MODEL]     = lb;
        out[(size_t)T_TOK * D_MODEL + 1] = g_zsum / (float)T_TOK;
    }
}

// ---------------- zero dispatch buffer ----------------
__global__ void zero_xe_kernel() {
    const size_t n = (size_t)E_NUM * CAPACITY * D_MODEL / 4;
    float4 z = make_float4(0.f, 0.f, 0.f, 0.f);
    float4* p = (float4*)g_xe;
    for (size_t i = (size_t)blockIdx.x * blockDim.x + threadIdx.x; i < n;
         i += (size_t)gridDim.x * blockDim.x)
        p[i] = z;
}

// ---------------- dispatch: scatter kept tokens into expert batches -------
__global__ void dispatch_kernel(const float* __restrict__ x) {
    const int j = blockIdx.x;           // 0..K*T-1, k-major
    const int r = g_rank[j];
    if (r < 0) return;
    const int t = j & (T_TOK - 1);
    const int e = g_topi[j];
    const float4* src = (const float4*)(x + (size_t)t * D_MODEL);
    float4* dst = (float4*)(g_xe + ((size_t)e * CAPACITY + r) * D_MODEL);
    dst[threadIdx.x] = src[threadIdx.x];   // 256 threads * float4 = 1024 floats
}

// ---------------- exact GELU ----------------
__device__ __forceinline__ float gelu_exact(float v) {
    return 0.5f * v * (1.f + erff(v * 0.70710678118654752440f));
}

// ---------------- batched SGEMM (128x128x8 tiles, 8x8 microtile) ----------
// FIRST:  g_h[e]    = gelu( g_xe[e](cap x D)  @ w_fc[e](D x HID) )
// !FIRST: g_oute[e] =        g_h[e](cap x HID) @ w_proj[e](HID x D)
template<bool FIRST>
__global__ void __launch_bounds__(256) sgemm_kernel(const float* __restrict__ Wall) {
    constexpr int Kd = FIRST ? D_MODEL : H_DIM;
    constexpr int N  = FIRST ? H_DIM   : D_MODEL;
    constexpr int M  = CAPACITY;

    const int e = blockIdx.z;
    const float* A = (FIRST ? g_xe : g_h)  + (size_t)e * M * Kd;
    const float* B = Wall                   + (size_t)e * Kd * N;
    float*       C = (FIRST ? g_h : g_oute) + (size_t)e * M * N;

    __shared__ float As[8][128];
    __shared__ float Bs[8][128];

    const int tid = threadIdx.x;
    const int tx = tid & 15;
    const int ty = tid >> 4;
    const int row0 = blockIdx.y * 128;
    const int col0 = blockIdx.x * 128;

    const int a_row = tid >> 1;         // 0..127
    const int a_c4  = (tid & 1) * 4;    // 0 or 4
    const int b_row = tid >> 5;         // 0..7
    const int b_c4  = (tid & 31) * 4;   // 0..124

    const float* Aptr = A + (size_t)(row0 + a_row) * Kd + a_c4;
    const float* Bptr = B + (size_t)b_row * N + col0 + b_c4;

    float acc[8][8];
#pragma unroll
    for (int i = 0; i < 8; i++)
#pragma unroll
        for (int j = 0; j < 8; j++) acc[i][j] = 0.f;

    for (int k0 = 0; k0 < Kd; k0 += 8) {
        float4 av = *(const float4*)(Aptr + k0);
        float4 bv = *(const float4*)(Bptr + (size_t)k0 * N);
        As[a_c4 + 0][a_row] = av.x;
        As[a_c4 + 1][a_row] = av.y;
        As[a_c4 + 2][a_row] = av.z;
        As[a_c4 + 3][a_row] = av.w;
        *(float4*)&Bs[b_row][b_c4] = bv;
        __syncthreads();

#pragma unroll
        for (int kk = 0; kk < 8; kk++) {
            float a[8], b[8];
#pragma unroll
            for (int i = 0; i < 8; i++) a[i] = As[kk][ty * 8 + i];
#pragma unroll
            for (int j = 0; j < 8; j++) b[j] = Bs[kk][tx * 8 + j];
#pragma unroll
            for (int i = 0; i < 8; i++)
#pragma unroll
                for (int j = 0; j < 8; j++) acc[i][j] += a[i] * b[j];
        }
        __syncthreads();
    }

#pragma unroll
    for (int i = 0; i < 8; i++) {
        float* crow = C + (size_t)(row0 + ty * 8 + i) * N + col0 + tx * 8;
#pragma unroll
        for (int j = 0; j < 8; j += 4) {
            float4 v;
            if (FIRST) {
                v.x = gelu_exact(acc[i][j + 0]);
                v.y = gelu_exact(acc[i][j + 1]);
                v.z = gelu_exact(acc[i][j + 2]);
                v.w = gelu_exact(acc[i][j + 3]);
            } else {
                v.x = acc[i][j + 0];
                v.y = acc[i][j + 1];
                v.z = acc[i][j + 2];
                v.w = acc[i][j + 3];
            }
            *(float4*)(crow + j) = v;
        }
    }
}

// ---------------- combine ----------------
__global__ void combine_kernel(float* __restrict__ out) {
    const int t = blockIdx.x;
    const int i = threadIdx.x;
    const int r0 = g_rank[t],          r1 = g_rank[T_TOK + t];
    const int e0 = g_topi[t],          e1 = g_topi[T_TOK + t];
    const float w0 = (r0 >= 0) ? g_p[t]         : 0.f;
    const float w1 = (r1 >= 0) ? g_p[T_TOK + t] : 0.f;
    const int s0 = (r0 >= 0) ? r0 : 0;
    const int s1 = (r1 >= 0) ? r1 : 0;
    const float4* a = (const float4*)(g_oute + ((size_t)e0 * CAPACITY + s0) * D_MODEL);
    const float4* b = (const float4*)(g_oute + ((size_t)e1 * CAPACITY + s1) * D_MODEL);
    float4 va = a[i], vb = b[i];
    float4 v;
    v.x = w0 * va.x + w1 * vb.x;
    v.y = w0 * va.y + w1 * vb.y;
    v.z = w0 * va.z + w1 * vb.z;
    v.w = w0 * va.w + w1 * vb.w;
    ((float4*)(out + (size_t)t * D_MODEL))[i] = v;
}

// ---------------- launch ----------------
extern "C" void kernel_launch(void* const* d_in, const int* in_sizes, int n_in,
                              void* d_out, int out_size) {
    const float* x     = (const float*)d_in[0];   // [B,S,D]
    const float* wg    = (const float*)d_in[1];   // [D,E]
    const float* wfc   = (const float*)d_in[2];   // [E,D,HID]
    const float* wproj = (const float*)d_in[3];   // [E,HID,D]
    float* out = (float*)d_out;
    const int write_tail = (out_size >= T_TOK * D_MODEL + 2);

    init_kernel<<<1, 32>>>();
    router_kernel<<<T_TOK, 128>>>(x, wg);
    zero_xe_kernel<<<2048, 256>>>();
    assign_kernel<<<1, 256>>>(out, write_tail);
    dispatch_kernel<<<K_TOP * T_TOK, 256>>>(x);

    sgemm_kernel<true ><<<dim3(H_DIM / 128, CAPACITY / 128, E_NUM), 256>>>(wfc);
    sgemm_kernel<false><<<dim3(D_MODEL / 128, CAPACITY / 128, E_NUM), 256>>>(wproj);

    combine_kernel<<<T_TOK, 256>>>(out);
}

// round 4
// speedup vs baseline: 2.6261x; 2.6261x over previous
#include <cuda_runtime.h>
#include <cstdint>
#include <cmath>

// ---------------- problem constants ----------------
#define T_TOK   4096
#define D_MODEL 1024
#define E_NUM   8
#define K_TOP   2
#define CAPACITY 1280
#define H_DIM   4096

// ---------------- device scratch ----------------
__device__ float g_xe  [(size_t)E_NUM * CAPACITY * D_MODEL];
__device__ float g_h   [(size_t)E_NUM * CAPACITY * H_DIM];
__device__ float g_oute[(size_t)E_NUM * CAPACITY * D_MODEL];
__device__ int   g_topi[K_TOP * T_TOK];
__device__ float g_p   [K_TOP * T_TOK];
__device__ int   g_rank[K_TOP * T_TOK];
__device__ float g_prob_sums[E_NUM];
__device__ float g_zsum;

// ---------------- helpers ----------------
__device__ __forceinline__ float tf32r(float x) {
    uint32_t u;
    asm("cvt.rna.tf32.f32 %0, %1;" : "=r"(u) : "f"(x));
    return __uint_as_float(u);
}
__device__ __forceinline__ float gelu_exact(float v) {
    return 0.5f * v * (1.f + erff(v * 0.70710678118654752440f));
}

#define MMA_TF32(c, a, b) \
    asm volatile("mma.sync.aligned.m16n8k8.row.col.f32.tf32.tf32.f32 " \
                 "{%0,%1,%2,%3}, {%4,%5,%6,%7}, {%8,%9}, {%0,%1,%2,%3};" \
                 : "+f"((c)[0]), "+f"((c)[1]), "+f"((c)[2]), "+f"((c)[3]) \
                 : "r"((a)[0]), "r"((a)[1]), "r"((a)[2]), "r"((a)[3]), \
                   "r"((b)[0]), "r"((b)[1]))

// ---------------- init ----------------
__global__ void init_kernel() {
    int i = threadIdx.x;
    if (i < E_NUM) g_prob_sums[i] = 0.f;
    if (i == 0)    g_zsum = 0.f;
}

// ---------------- router ----------------
__global__ void router_kernel(const float* __restrict__ x,
                              const float* __restrict__ wg) {
    const int t = blockIdx.x;
    const float* xr = x + (size_t)t * D_MODEL;

    float acc[E_NUM];
#pragma unroll
    for (int e = 0; e < E_NUM; e++) acc[e] = 0.f;
    for (int d = threadIdx.x; d < D_MODEL; d += 128) {
        float xv = xr[d];
        const float* w = wg + d * E_NUM;
#pragma unroll
        for (int e = 0; e < E_NUM; e++) acc[e] += xv * w[e];
    }
    __shared__ float red[E_NUM][128];
#pragma unroll
    for (int e = 0; e < E_NUM; e++) red[e][threadIdx.x] = acc[e];
    __syncthreads();
    __shared__ float logit[E_NUM];
    if (threadIdx.x < E_NUM) {
        float s = 0.f;
        for (int i = 0; i < 128; i++) s += red[threadIdx.x][i];
        logit[threadIdx.x] = s;
    }
    __syncthreads();
    if (threadIdx.x == 0) {
        float l[E_NUM];
#pragma unroll
        for (int e = 0; e < E_NUM; e++) l[e] = logit[e];
        float m = l[0];
#pragma unroll
        for (int e = 1; e < E_NUM; e++) m = fmaxf(m, l[e]);
        float se = 0.f;
#pragma unroll
        for (int e = 0; e < E_NUM; e++) se += expf(l[e] - m);
        float inv = 1.f / se;
#pragma unroll
        for (int e = 0; e < E_NUM; e++)
            atomicAdd(&g_prob_sums[e], expf(l[e] - m) * inv);
        float lse = m + logf(se);
        atomicAdd(&g_zsum, lse * lse);

        float v1 = -3.4e38f, v2 = -3.4e38f;
        int i1 = 0, i2 = 0;
#pragma unroll
        for (int e = 0; e < E_NUM; e++) {
            float v = l[e];
            if (v > v1) { v2 = v1; i2 = i1; v1 = v; i1 = e; }
            else if (v > v2) { v2 = v; i2 = e; }
        }
        float e2 = expf(v2 - v1);
        float s2 = 1.f + e2;
        g_topi[t]         = i1;
        g_topi[T_TOK + t] = i2;
        g_p[t]            = 1.f / s2;
        g_p[T_TOK + t]    = e2 / s2;
    }
}

// ---------------- capacity assignment ----------------
__global__ void assign_kernel(float* __restrict__ out, int write_tail) {
    __shared__ int hist[256][E_NUM];
    __shared__ int tot[E_NUM];
    const int tid = threadIdx.x;
    const int base = tid * 32;

    int cnt[E_NUM];
#pragma unroll
    for (int e = 0; e < E_NUM; e++) cnt[e] = 0;
    for (int j = 0; j < 32; j++) cnt[g_topi[base + j]]++;
#pragma unroll
    for (int e = 0; e < E_NUM; e++) hist[tid][e] = cnt[e];
    __syncthreads();
    if (tid < E_NUM) {
        int s = 0;
        for (int i = 0; i < 256; i++) { int c = hist[i][tid]; hist[i][tid] = s; s += c; }
        tot[tid] = s;
    }
    __syncthreads();
    int run[E_NUM];
#pragma unroll
    for (int e = 0; e < E_NUM; e++) run[e] = hist[tid][e];
    for (int j = 0; j < 32; j++) {
        int idx = base + j;
        int e = g_topi[idx];
        int r = run[e]++;
        g_rank[idx] = (r < CAPACITY) ? r : -1;
    }
    if (tid == 0 && write_tail) {
        float lb = 0.f;
#pragma unroll
        for (int e = 0; e < E_NUM; e++) {
            int kc = tot[e] < CAPACITY ? tot[e] : CAPACITY;
            lb += (g_prob_sums[e] / (float)T_TOK) *
                  ((float)kc / (float)(T_TOK * K_TOP));
        }
        lb *= (float)E_NUM;
        out[(size_t)T_TOK * D_MODEL]     = lb;
        out[(size_t)T_TOK * D_MODEL + 1] = g_zsum / (float)T_TOK;
    }
}

// ---------------- zero dispatch buffer ----------------
__global__ void zero_xe_kernel() {
    const size_t n = (size_t)E_NUM * CAPACITY * D_MODEL / 4;
    float4 z = make_float4(0.f, 0.f, 0.f, 0.f);
    float4* p = (float4*)g_xe;
    for (size_t i = (size_t)blockIdx.x * blockDim.x + threadIdx.x; i < n;
         i += (size_t)gridDim.x * blockDim.x)
        p[i] = z;
}

// ---------------- dispatch ----------------
__global__ void dispatch_kernel(const float* __restrict__ x) {
    const int j = blockIdx.x;
    const int r = g_rank[j];
    if (r < 0) return;
    const int t = j & (T_TOK - 1);
    const int e = g_topi[j];
    const float4* src = (const float4*)(x + (size_t)t * D_MODEL);
    float4* dst = (float4*)(g_xe + ((size_t)e * CAPACITY + r) * D_MODEL);
    dst[threadIdx.x] = src[threadIdx.x];
}

// ---------------- tf32 warp-MMA GEMM -------------------------------------
// C[M=1280, Nt] = A[M, Kd] @ B[Kd, Nt]   (B native [K][N] layout, no transpose)
// FIRST:  g_h = gelu(g_xe @ w_fc)    Kd=1024, Nt=4096
// !FIRST: g_oute = g_h @ w_proj      Kd=4096, Nt=1024
#define ASTR 20    // A smem row stride (floats)
#define BSTR 136   // B smem row stride (floats)

template<bool FIRST>
__global__ void __launch_bounds__(256, 2) gemm_mma_kernel(const float* __restrict__ W) {
    constexpr int Kd = FIRST ? D_MODEL : H_DIM;
    constexpr int Nt = FIRST ? H_DIM   : D_MODEL;
    constexpr int NIT = Kd / 16;

    __shared__ __align__(16) float As[2][128 * ASTR];   // [m][k] padded
    __shared__ __align__(16) float Bs[2][16 * BSTR];    // [k][n] padded

    const int tid  = threadIdx.x;
    const int wid  = tid >> 5;
    const int lane = tid & 31;
    const int gid  = lane >> 2;   // 0..7
    const int tig  = lane & 3;    // 0..3
    const int warpM = wid & 1;    // 2 warps x 64 rows
    const int warpN = wid >> 1;   // 4 warps x 32 cols

    const int e    = blockIdx.z;
    const int row0 = blockIdx.y * 128;
    const int col0 = blockIdx.x * 128;

    const float* Ab = (FIRST ? g_xe : g_h) + (size_t)e * CAPACITY * Kd + (size_t)row0 * Kd;
    const float* Bb = W + (size_t)e * Kd * Nt + col0;
    float* C = (FIRST ? g_h : g_oute) + (size_t)e * CAPACITY * Nt;

    // loaders: A tile 128x16 -> 2 float4/thread ; B tile 16x128 -> 2 float4/thread
    const int arow = tid >> 1;           // 0..127
    const int ac   = (tid & 1) * 8;      // 0 or 8
    const int brow = tid >> 4;           // 0..15
    const int bcol = (tid & 15) * 8;     // 0..120

    const float* Aptr = Ab + (size_t)arow * Kd + ac;
    const float* Bptr = Bb + (size_t)brow * Nt + bcol;

    float c[4][4][4];
#pragma unroll
    for (int i = 0; i < 4; i++)
#pragma unroll
        for (int j = 0; j < 4; j++)
#pragma unroll
            for (int q = 0; q < 4; q++) c[i][j][q] = 0.f;

    float4 cA0 = *(const float4*)(Aptr);
    float4 cA1 = *(const float4*)(Aptr + 4);
    float4 cB0 = *(const float4*)(Bptr);
    float4 cB1 = *(const float4*)(Bptr + 4);

    for (int it = 0; it < NIT; it++) {
        const int s = it & 1;
        float* dA = &As[s][arow * ASTR + ac];
        dA[0] = tf32r(cA0.x); dA[1] = tf32r(cA0.y); dA[2] = tf32r(cA0.z); dA[3] = tf32r(cA0.w);
        dA[4] = tf32r(cA1.x); dA[5] = tf32r(cA1.y); dA[6] = tf32r(cA1.z); dA[7] = tf32r(cA1.w);
        float* dB = &Bs[s][brow * BSTR + bcol];
        dB[0] = tf32r(cB0.x); dB[1] = tf32r(cB0.y); dB[2] = tf32r(cB0.z); dB[3] = tf32r(cB0.w);
        dB[4] = tf32r(cB1.x); dB[5] = tf32r(cB1.y); dB[6] = tf32r(cB1.z); dB[7] = tf32r(cB1.w);

        // prefetch next tile into registers (global, independent of smem)
        if (it + 1 < NIT) {
            const float* nAp = Aptr + (it + 1) * 16;
            const float* nBp = Bptr + (size_t)(it + 1) * 16 * Nt;
            cA0 = *(const float4*)(nAp);
            cA1 = *(const float4*)(nAp + 4);
            cB0 = *(const float4*)(nBp);
            cB1 = *(const float4*)(nBp + 4);
        }
        __syncthreads();

        const float* as = As[s];
        const float* bs = Bs[s];
#pragma unroll
        for (int ks = 0; ks < 16; ks += 8) {
            uint32_t a[4][4], b[4][2];
#pragma unroll
            for (int i = 0; i < 4; i++) {
                const int r = warpM * 64 + i * 16 + gid;
                a[i][0] = __float_as_uint(as[r * ASTR + ks + tig]);
                a[i][1] = __float_as_uint(as[(r + 8) * ASTR + ks + tig]);
                a[i][2] = __float_as_uint(as[r * ASTR + ks + tig + 4]);
                a[i][3] = __float_as_uint(as[(r + 8) * ASTR + ks + tig + 4]);
            }
#pragma unroll
            for (int j = 0; j < 4; j++) {
                const int n = warpN * 32 + j * 8 + gid;
                b[j][0] = __float_as_uint(bs[(ks + tig) * BSTR + n]);
                b[j][1] = __float_as_uint(bs[(ks + tig + 4) * BSTR + n]);
            }
#pragma unroll
            for (int i = 0; i < 4; i++)
#pragma unroll
                for (int j = 0; j < 4; j++)
                    MMA_TF32(c[i][j], a[i], b[j]);
        }
        __syncthreads();
    }

    // epilogue
#pragma unroll
    for (int i = 0; i < 4; i++) {
        const int r = row0 + warpM * 64 + i * 16 + gid;
#pragma unroll
        for (int j = 0; j < 4; j++) {
            const int n = col0 + warpN * 32 + j * 8 + tig * 2;
            float2 v0, v1;
            if (FIRST) {
                v0.x = gelu_exact(c[i][j][0]); v0.y = gelu_exact(c[i][j][1]);
                v1.x = gelu_exact(c[i][j][2]); v1.y = gelu_exact(c[i][j][3]);
            } else {
                v0.x = c[i][j][0]; v0.y = c[i][j][1];
                v1.x = c[i][j][2]; v1.y = c[i][j][3];
            }
            *(float2*)&C[(size_t)r * Nt + n]       = v0;
            *(float2*)&C[(size_t)(r + 8) * Nt + n] = v1;
        }
    }
}

// ---------------- combine ----------------
__global__ void combine_kernel(float* __restrict__ out) {
    const int t = blockIdx.x;
    const int i = threadIdx.x;
    const int r0 = g_rank[t],          r1 = g_rank[T_TOK + t];
    const int e0 = g_topi[t],          e1 = g_topi[T_TOK + t];
    const float w0 = (r0 >= 0) ? g_p[t]         : 0.f;
    const float w1 = (r1 >= 0) ? g_p[T_TOK + t] : 0.f;
    const int s0 = (r0 >= 0) ? r0 : 0;
    const int s1 = (r1 >= 0) ? r1 : 0;
    const float4* a = (const float4*)(g_oute + ((size_t)e0 * CAPACITY + s0) * D_MODEL);
    const float4* b = (const float4*)(g_oute + ((size_t)e1 * CAPACITY + s1) * D_MODEL);
    float4 va = a[i], vb = b[i];
    float4 v;
    v.x = w0 * va.x + w1 * vb.x;
    v.y = w0 * va.y + w1 * vb.y;
    v.z = w0 * va.z + w1 * vb.z;
    v.w = w0 * va.w + w1 * vb.w;
    ((float4*)(out + (size_t)t * D_MODEL))[i] = v;
}

// ---------------- launch ----------------
extern "C" void kernel_launch(void* const* d_in, const int* in_sizes, int n_in,
                              void* d_out, int out_size) {
    const float* x     = (const float*)d_in[0];
    const float* wg    = (const float*)d_in[1];
    const float* wfc   = (const float*)d_in[2];   // [E, D, HID]
    const float* wproj = (const float*)d_in[3];   // [E, HID, D]
    float* out = (float*)d_out;
    const int write_tail = (out_size >= T_TOK * D_MODEL + 2);

    init_kernel<<<1, 32>>>();
    router_kernel<<<T_TOK, 128>>>(x, wg);
    zero_xe_kernel<<<2048, 256>>>();
    assign_kernel<<<1, 256>>>(out, write_tail);
    dispatch_kernel<<<K_TOP * T_TOK, 256>>>(x);

    gemm_mma_kernel<true ><<<dim3(H_DIM / 128, CAPACITY / 128, E_NUM), 256>>>(wfc);
    gemm_mma_kernel<false><<<dim3(D_MODEL / 128, CAPACITY / 128, E_NUM), 256>>>(wproj);

    combine_kernel<<<T_TOK, 256>>>(out);
}

// round 5
// speedup vs baseline: 3.6476x; 1.3890x over previous
#include <cuda_runtime.h>
#include <cstdint>
#include <cmath>

// ---------------- problem constants ----------------
#define T_TOK   4096
#define D_MODEL 1024
#define E_NUM   8
#define K_TOP   2
#define CAPACITY 1280
#define H_DIM   4096

// ---------------- device scratch ----------------
__device__ float g_xe  [(size_t)E_NUM * CAPACITY * D_MODEL];
__device__ float g_h   [(size_t)E_NUM * CAPACITY * H_DIM];
__device__ float g_oute[(size_t)E_NUM * CAPACITY * D_MODEL];
__device__ int   g_topi[K_TOP * T_TOK];
__device__ float g_p   [K_TOP * T_TOK];
__device__ int   g_rank[K_TOP * T_TOK];
__device__ int   g_blkcnt[E_NUM];        // 128-row blocks actually used per expert
__device__ float g_prob_sums[E_NUM];
__device__ float g_zsum;

// ---------------- helpers ----------------
__device__ __forceinline__ float tf32r(float x) {
    uint32_t u;
    asm("cvt.rna.tf32.f32 %0, %1;" : "=r"(u) : "f"(x));
    return __uint_as_float(u);
}
__device__ __forceinline__ uint32_t tf32u(float x) {
    uint32_t u;
    asm("cvt.rna.tf32.f32 %0, %1;" : "=r"(u) : "f"(x));
    return u;
}
__device__ __forceinline__ float gelu_exact(float v) {
    return 0.5f * v * (1.f + erff(v * 0.70710678118654752440f));
}

#define CP16(dst, src) \
    asm volatile("cp.async.cg.shared.global [%0], [%1], 16;" \
                 :: "r"(dst), "l"(src) : "memory")
#define CPCOMMIT() asm volatile("cp.async.commit_group;" ::: "memory")
#define CPWAIT1()  asm volatile("cp.async.wait_group 1;" ::: "memory")

#define MMA_TF32(c, a, b) \
    asm volatile("mma.sync.aligned.m16n8k8.row.col.f32.tf32.tf32.f32 " \
                 "{%0,%1,%2,%3}, {%4,%5,%6,%7}, {%8,%9}, {%0,%1,%2,%3};" \
                 : "+f"((c)[0]), "+f"((c)[1]), "+f"((c)[2]), "+f"((c)[3]) \
                 : "r"((a)[0]), "r"((a)[1]), "r"((a)[2]), "r"((a)[3]), \
                   "r"((b)[0]), "r"((b)[1]))

// ---------------- init ----------------
__global__ void init_kernel() {
    int i = threadIdx.x;
    if (i < E_NUM) g_prob_sums[i] = 0.f;
    if (i == 0)    g_zsum = 0.f;
}

// ---------------- router ----------------
__global__ void router_kernel(const float* __restrict__ x,
                              const float* __restrict__ wg) {
    const int t = blockIdx.x;
    const float* xr = x + (size_t)t * D_MODEL;

    float acc[E_NUM];
#pragma unroll
    for (int e = 0; e < E_NUM; e++) acc[e] = 0.f;
    for (int d = threadIdx.x; d < D_MODEL; d += 128) {
        float xv = xr[d];
        const float* w = wg + d * E_NUM;
#pragma unroll
        for (int e = 0; e < E_NUM; e++) acc[e] += xv * w[e];
    }
    __shared__ float red[E_NUM][128];
#pragma unroll
    for (int e = 0; e < E_NUM; e++) red[e][threadIdx.x] = acc[e];
    __syncthreads();
    __shared__ float logit[E_NUM];
    if (threadIdx.x < E_NUM) {
        float s = 0.f;
        for (int i = 0; i < 128; i++) s += red[threadIdx.x][i];
        logit[threadIdx.x] = s;
    }
    __syncthreads();
    if (threadIdx.x == 0) {
        float l[E_NUM];
#pragma unroll
        for (int e = 0; e < E_NUM; e++) l[e] = logit[e];
        float m = l[0];
#pragma unroll
        for (int e = 1; e < E_NUM; e++) m = fmaxf(m, l[e]);
        float se = 0.f;
#pragma unroll
        for (int e = 0; e < E_NUM; e++) se += expf(l[e] - m);
        float inv = 1.f / se;
#pragma unroll
        for (int e = 0; e < E_NUM; e++)
            atomicAdd(&g_prob_sums[e], expf(l[e] - m) * inv);
        float lse = m + logf(se);
        atomicAdd(&g_zsum, lse * lse);

        float v1 = -3.4e38f, v2 = -3.4e38f;
        int i1 = 0, i2 = 0;
#pragma unroll
        for (int e = 0; e < E_NUM; e++) {
            float v = l[e];
            if (v > v1) { v2 = v1; i2 = i1; v1 = v; i1 = e; }
            else if (v > v2) { v2 = v; i2 = e; }
        }
        float e2 = expf(v2 - v1);
        float s2 = 1.f + e2;
        g_topi[t]         = i1;
        g_topi[T_TOK + t] = i2;
        g_p[t]            = 1.f / s2;
        g_p[T_TOK + t]    = e2 / s2;
    }
}

// ---------------- capacity assignment ----------------
__global__ void assign_kernel(float* __restrict__ out, int write_tail) {
    __shared__ int hist[256][E_NUM];
    __shared__ int tot[E_NUM];
    const int tid = threadIdx.x;
    const int base = tid * 32;

    int cnt[E_NUM];
#pragma unroll
    for (int e = 0; e < E_NUM; e++) cnt[e] = 0;
    for (int j = 0; j < 32; j++) cnt[g_topi[base + j]]++;
#pragma unroll
    for (int e = 0; e < E_NUM; e++) hist[tid][e] = cnt[e];
    __syncthreads();
    if (tid < E_NUM) {
        int s = 0;
        for (int i = 0; i < 256; i++) { int c = hist[i][tid]; hist[i][tid] = s; s += c; }
        tot[tid] = s;
        int kc = s < CAPACITY ? s : CAPACITY;
        g_blkcnt[tid] = (kc + 127) >> 7;      // 128-row blocks used
    }
    __syncthreads();
    int run[E_NUM];
#pragma unroll
    for (int e = 0; e < E_NUM; e++) run[e] = hist[tid][e];
    for (int j = 0; j < 32; j++) {
        int idx = base + j;
        int e = g_topi[idx];
        int r = run[e]++;
        g_rank[idx] = (r < CAPACITY) ? r : -1;
    }
    if (tid == 0 && write_tail) {
        float lb = 0.f;
#pragma unroll
        for (int e = 0; e < E_NUM; e++) {
            int kc = tot[e] < CAPACITY ? tot[e] : CAPACITY;
            lb += (g_prob_sums[e] / (float)T_TOK) *
                  ((float)kc / (float)(T_TOK * K_TOP));
        }
        lb *= (float)E_NUM;
        out[(size_t)T_TOK * D_MODEL]     = lb;
        out[(size_t)T_TOK * D_MODEL + 1] = g_zsum / (float)T_TOK;
    }
}

// ---------------- zero dispatch buffer ----------------
__global__ void zero_xe_kernel() {
    const size_t n = (size_t)E_NUM * CAPACITY * D_MODEL / 4;
    float4 z = make_float4(0.f, 0.f, 0.f, 0.f);
    float4* p = (float4*)g_xe;
    for (size_t i = (size_t)blockIdx.x * blockDim.x + threadIdx.x; i < n;
         i += (size_t)gridDim.x * blockDim.x)
        p[i] = z;
}

// ---------------- dispatch (tf32-round x at the source) ----------------
__global__ void dispatch_kernel(const float* __restrict__ x) {
    const int j = blockIdx.x;
    const int r = g_rank[j];
    if (r < 0) return;
    const int t = j & (T_TOK - 1);
    const int e = g_topi[j];
    const float4* src = (const float4*)(x + (size_t)t * D_MODEL);
    float4* dst = (float4*)(g_xe + ((size_t)e * CAPACITY + r) * D_MODEL);
    float4 v = src[threadIdx.x];
    v.x = tf32r(v.x); v.y = tf32r(v.y);
    v.z = tf32r(v.z); v.w = tf32r(v.w);
    dst[threadIdx.x] = v;
}

// ---------------- tf32 warp-MMA GEMM, 3-stage cp.async -------------------
// C[M, Nt] = A[M, Kd] @ B[Kd, Nt]  (B native [K][N] layout)
// FIRST:  g_h = tf32(gelu(g_xe @ w_fc))   Kd=1024, Nt=4096
// !FIRST: g_oute = g_h @ w_proj           Kd=4096, Nt=1024
#define ASTR 20            // A smem row stride (floats)
#define BSTR 136           // B smem row stride (floats)
#define ASZ  (128 * ASTR)  // floats per A stage
#define BSZ  (16 * BSTR)   // floats per B stage
#define GEMM_SMEM ((3 * (ASZ + BSZ)) * 4)

template<bool FIRST>
__global__ void __launch_bounds__(256, 2) gemm_mma_kernel(const float* __restrict__ W) {
    constexpr int Kd = FIRST ? D_MODEL : H_DIM;
    constexpr int Nt = FIRST ? H_DIM   : D_MODEL;
    constexpr int NIT = Kd / 16;

    const int e = blockIdx.z;
    if ((int)blockIdx.y >= g_blkcnt[e]) return;   // empty row-block: skip

    extern __shared__ __align__(16) float smem[];
    float* Asm = smem;                // [3][ASZ]
    float* Bsm = smem + 3 * ASZ;      // [3][BSZ]

    const int tid  = threadIdx.x;
    const int wid  = tid >> 5;
    const int lane = tid & 31;
    const int gid  = lane >> 2;   // 0..7
    const int tig  = lane & 3;    // 0..3
    const int warpM = wid & 1;    // 2 warps x 64 rows
    const int warpN = wid >> 1;   // 4 warps x 32 cols

    const int row0 = blockIdx.y * 128;
    const int col0 = blockIdx.x * 128;

    const float* Ab = (FIRST ? g_xe : g_h) + (size_t)e * CAPACITY * Kd + (size_t)row0 * Kd;
    const float* Bb = W + (size_t)e * Kd * Nt + col0;
    float* C = (FIRST ? g_h : g_oute) + (size_t)e * CAPACITY * Nt;

    // loaders: A tile 128x16, B tile 16x128 -> 2 float4/thread each
    const int arow = tid >> 1;           // 0..127
    const int ac   = (tid & 1) * 8;      // 0 or 8
    const int brow = tid >> 4;           // 0..15
    const int bcol = (tid & 15) * 8;     // 0..120

    const float* Aptr = Ab + (size_t)arow * Kd + ac;
    const float* Bptr = Bb + (size_t)brow * Nt + bcol;
    const uint32_t aBase = (uint32_t)__cvta_generic_to_shared(Asm) + (arow * ASTR + ac) * 4;
    const uint32_t bBase = (uint32_t)__cvta_generic_to_shared(Bsm) + (brow * BSTR + bcol) * 4;

    float c[4][4][4];
#pragma unroll
    for (int i = 0; i < 4; i++)
#pragma unroll
        for (int j = 0; j < 4; j++)
#pragma unroll
            for (int q = 0; q < 4; q++) c[i][j][q] = 0.f;

    // prologue: stages 0,1
    {
        CP16(aBase, Aptr);
        CP16(aBase + 16, Aptr + 4);
        CP16(bBase, Bptr);
        CP16(bBase + 16, Bptr + 4);
        CPCOMMIT();
        const float* pa = Aptr + 16;
        const float* pb = Bptr + (size_t)16 * Nt;
        CP16(aBase + ASZ * 4, pa);
        CP16(aBase + ASZ * 4 + 16, pa + 4);
        CP16(bBase + BSZ * 4, pb);
        CP16(bBase + BSZ * 4 + 16, pb + 4);
        CPCOMMIT();
    }

    int s = 0;
    for (int it = 0; it < NIT; it++) {
        CPWAIT1();
        __syncthreads();

        // issue stage it+2 into slot (s+2)%3
        if (it + 2 < NIT) {
            const int sn = (s + 2 >= 3) ? s - 1 : s + 2;
            const float* pa = Aptr + (it + 2) * 16;
            const float* pb = Bptr + (size_t)(it + 2) * 16 * Nt;
            const uint32_t da = aBase + (uint32_t)(sn * ASZ * 4);
            const uint32_t db = bBase + (uint32_t)(sn * BSZ * 4);
            CP16(da, pa);
            CP16(da + 16, pa + 4);
            CP16(db, pb);
            CP16(db + 16, pb + 4);
        }
        CPCOMMIT();

        const float* as = Asm + s * ASZ;
        const float* bs = Bsm + s * BSZ;
#pragma unroll
        for (int ks = 0; ks < 16; ks += 8) {
            uint32_t a[4][4], b[4][2];
#pragma unroll
            for (int i = 0; i < 4; i++) {
                const int r = warpM * 64 + i * 16 + gid;
                a[i][0] = __float_as_uint(as[r * ASTR + ks + tig]);
                a[i][1] = __float_as_uint(as[(r + 8) * ASTR + ks + tig]);
                a[i][2] = __float_as_uint(as[r * ASTR + ks + tig + 4]);
                a[i][3] = __float_as_uint(as[(r + 8) * ASTR + ks + tig + 4]);
            }
#pragma unroll
            for (int j = 0; j < 4; j++) {
                const int n = warpN * 32 + j * 8 + gid;
                b[j][0] = tf32u(bs[(ks + tig) * BSTR + n]);
                b[j][1] = tf32u(bs[(ks + tig + 4) * BSTR + n]);
            }
#pragma unroll
            for (int i = 0; i < 4; i++)
#pragma unroll
                for (int j = 0; j < 4; j++)
                    MMA_TF32(c[i][j], a[i], b[j]);
        }
        s = (s + 1 >= 3) ? 0 : s + 1;
    }

    // epilogue
#pragma unroll
    for (int i = 0; i < 4; i++) {
        const int r = row0 + warpM * 64 + i * 16 + gid;
#pragma unroll
        for (int j = 0; j < 4; j++) {
            const int n = col0 + warpN * 32 + j * 8 + tig * 2;
            float2 v0, v1;
            if (FIRST) {
                v0.x = tf32r(gelu_exact(c[i][j][0])); v0.y = tf32r(gelu_exact(c[i][j][1]));
                v1.x = tf32r(gelu_exact(c[i][j][2])); v1.y = tf32r(gelu_exact(c[i][j][3]));
            } else {
                v0.x = c[i][j][0]; v0.y = c[i][j][1];
                v1.x = c[i][j][2]; v1.y = c[i][j][3];
            }
            *(float2*)&C[(size_t)r * Nt + n]       = v0;
            *(float2*)&C[(size_t)(r + 8) * Nt + n] = v1;
        }
    }
}

// ---------------- combine ----------------
__global__ void combine_kernel(float* __restrict__ out) {
    const int t = blockIdx.x;
    const int i = threadIdx.x;
    const int r0 = g_rank[t],          r1 = g_rank[T_TOK + t];
    const int e0 = g_topi[t],          e1 = g_topi[T_TOK + t];
    const float w0 = (r0 >= 0) ? g_p[t]         : 0.f;
    const float w1 = (r1 >= 0) ? g_p[T_TOK + t] : 0.f;
    const int s0 = (r0 >= 0) ? r0 : 0;
    const int s1 = (r1 >= 0) ? r1 : 0;
    const float4* a = (const float4*)(g_oute + ((size_t)e0 * CAPACITY + s0) * D_MODEL);
    const float4* b = (const float4*)(g_oute + ((size_t)e1 * CAPACITY + s1) * D_MODEL);
    float4 va = a[i], vb = b[i];
    float4 v;
    v.x = w0 * va.x + w1 * vb.x;
    v.y = w0 * va.y + w1 * vb.y;
    v.z = w0 * va.z + w1 * vb.z;
    v.w = w0 * va.w + w1 * vb.w;
    ((float4*)(out + (size_t)t * D_MODEL))[i] = v;
}

// ---------------- launch ----------------
extern "C" void kernel_launch(void* const* d_in, const int* in_sizes, int n_in,
                              void* d_out, int out_size) {
    const float* x     = (const float*)d_in[0];
    const float* wg    = (const float*)d_in[1];
    const float* wfc   = (const float*)d_in[2];   // [E, D, HID]
    const float* wproj = (const float*)d_in[3];   // [E, HID, D]
    float* out = (float*)d_out;
    const int write_tail = (out_size >= T_TOK * D_MODEL + 2);

    static int attr_done = 0;
    if (!attr_done) {
        cudaFuncSetAttribute((const void*)gemm_mma_kernel<true>,
                             cudaFuncAttributeMaxDynamicSharedMemorySize, GEMM_SMEM);
        cudaFuncSetAttribute((const void*)gemm_mma_kernel<false>,
                             cudaFuncAttributeMaxDynamicSharedMemorySize, GEMM_SMEM);
        attr_done = 1;
    }

    init_kernel<<<1, 32>>>();
    router_kernel<<<T_TOK, 128>>>(x, wg);
    zero_xe_kernel<<<2048, 256>>>();
    assign_kernel<<<1, 256>>>(out, write_tail);
    dispatch_kernel<<<K_TOP * T_TOK, 256>>>(x);

    gemm_mma_kernel<true ><<<dim3(H_DIM / 128, CAPACITY / 128, E_NUM), 256, GEMM_SMEM>>>(wfc);
    gemm_mma_kernel<false><<<dim3(D_MODEL / 128, CAPACITY / 128, E_NUM), 256, GEMM_SMEM>>>(wproj);

    combine_kernel<<<T_TOK, 256>>>(out);
}